// round 16
// baseline (speedup 1.0000x reference)
#include <cuda_runtime.h>
#include <math_constants.h>

#define NB 8
#define NPTS 4096
#define KNN 16
#define MPTS (NB * NPTS)
#define CH 32
#define NCLS 40

__device__ int    g_knn[MPTS * KNN];
__device__ float  g_y[MPTS * CH];
__device__ float4 g_feat[MPTS * 17];
__device__ float  g_pool[NB * CH];
__device__ int    g_done;

__device__ __forceinline__ float safe_norm3(float x, float y, float z) {
    float s = x * x + y * y + z * z;
    return s > 0.f ? sqrtf(s) : 0.f;
}

__device__ __forceinline__ float angle3(float ax, float ay, float az,
                                        float bx, float by, float bz) {
    float cx = ay * bz - az * by;
    float cy = az * bx - ax * bz;
    float cz = ax * by - ay * bx;
    float cn = safe_norm3(cx, cy, cz);
    float d  = ax * bx + ay * by + az * bz;
    bool ok = (cn > 0.f) || (d != 0.f);
    return ok ? atan2f(cn, d) : 0.f;
}

// ---------------------------------------------------------------------------
// kNN v8b (proven R13): two-pass threshold-primed warp-select.
// Block 0 additionally zeroes g_pool and g_done (consumed 2 launches later).
// ---------------------------------------------------------------------------
__global__ __launch_bounds__(256) void knn_kernel(const float* __restrict__ pos) {
    const unsigned FULL = 0xFFFFFFFFu;
    const float INF = CUDART_INF_F;

    if (blockIdx.x == 0) {
        if (threadIdx.x < NB * CH) g_pool[threadIdx.x] = 0.f;
        if (threadIdx.x == 0) g_done = 0;
    }

    int lane = threadIdx.x & 31;
    int warp = threadIdx.x >> 5;
    int half = lane >> 4;
    int lh   = lane & 15;
    int hsh  = half << 4;

    int qbase = blockIdx.x * 16;
    int q0    = qbase + warp * 2;          // even
    int batch = blockIdx.x >> 8;
    int q0l   = q0 & (NPTS - 1);
    int q1l   = q0l + 1;
    int selfb = q0l & ~31;

    float p0x = pos[3 * q0 + 0], p0y = pos[3 * q0 + 1], p0z = pos[3 * q0 + 2];
    float p1x = pos[3 * q0 + 3], p1y = pos[3 * q0 + 4], p1z = pos[3 * q0 + 5];
    float m2x0 = -2.f * p0x, m2y0 = -2.f * p0y, m2z0 = -2.f * p0z;
    float m2x1 = -2.f * p1x, m2y1 = -2.f * p1y, m2z1 = -2.f * p1z;

    const float* bp = pos + (size_t)batch * NPTS * 3;
    __shared__ float4 tile[1024];          // 16 KB

    // pass 1: per-lane running mins
    float min0 = INF, min1 = INF;
    for (int t = 0; t < NPTS; t += 1024) {
        __syncthreads();
#pragma unroll
        for (int u = 0; u < 4; u++) {
            int p = t + threadIdx.x + u * 256;
            float cx = bp[3 * p + 0], cy = bp[3 * p + 1], cz = bp[3 * p + 2];
            tile[threadIdx.x + u * 256] =
                make_float4(cx, cy, cz, cx * cx + cy * cy + cz * cz);
        }
        __syncthreads();
#pragma unroll 4
        for (int s = 0; s < 32; s++) {
            int base = t + s * 32;
            float4 c = tile[s * 32 + lane];
            float d0 = fmaf(c.x, m2x0, fmaf(c.y, m2y0, fmaf(c.z, m2z0, c.w)));
            float d1 = fmaf(c.x, m2x1, fmaf(c.y, m2y1, fmaf(c.z, m2z1, c.w)));
            if (base == selfb) {
                int cl = base + lane;
                if (cl == q0l) d0 = INF;
                if (cl == q1l) d1 = INF;
            }
            min0 = fminf(min0, d0);
            min1 = fminf(min1, d1);
        }
    }

    // tau: 16th smallest of the 32 lane-mins
    float L = INF;
#pragma unroll 8
    for (int src = 0; src < 32; src++) {
        float v0 = __shfl_sync(FULL, min0, src);
        float v1 = __shfl_sync(FULL, min1, src);
        float v = half ? v1 : v0;
        unsigned ble = __ballot_sync(FULL, L <= v);
        int pos_ = __popc((ble >> hsh) & 0xFFFFu);
        float Lup = __shfl_up_sync(FULL, L, 1);
        if (lh == pos_)      L = v;
        else if (lh > pos_)  L = Lup;
    }
    float t0e = nextafterf(__shfl_sync(FULL, L, 15), INF);
    float t1e = nextafterf(__shfl_sync(FULL, L, 31), INF);

    // pass 2: exact selection under primed threshold
    L = INF;
    int LI = batch * NPTS;
    float tp0 = t0e, tp1 = t1e;

    for (int t = 0; t < NPTS; t += 1024) {
        __syncthreads();
#pragma unroll
        for (int u = 0; u < 4; u++) {
            int p = t + threadIdx.x + u * 256;
            float cx = bp[3 * p + 0], cy = bp[3 * p + 1], cz = bp[3 * p + 2];
            tile[threadIdx.x + u * 256] =
                make_float4(cx, cy, cz, cx * cx + cy * cy + cz * cz);
        }
        __syncthreads();
#pragma unroll 4
        for (int s = 0; s < 32; s++) {
            int base = t + s * 32;
            float4 c = tile[s * 32 + lane];
            float d0 = fmaf(c.x, m2x0, fmaf(c.y, m2y0, fmaf(c.z, m2z0, c.w)));
            float d1 = fmaf(c.x, m2x1, fmaf(c.y, m2y1, fmaf(c.z, m2z1, c.w)));
            if (base == selfb) {
                int cl = base + lane;
                if (cl == q0l) d0 = INF;
                if (cl == q1l) d1 = INF;
            }
            unsigned bal0 = __ballot_sync(FULL, d0 < tp0);
            unsigned bal1 = __ballot_sync(FULL, d1 < tp1);
            while (bal0 | bal1) {
                int s0 = __ffs(bal0) - 1;
                int s1 = __ffs(bal1) - 1;
                float v0 = __shfl_sync(FULL, d0, bal0 ? s0 : 0);
                float v1 = __shfl_sync(FULL, d1, bal1 ? s1 : 0);
                float v;
                int   vi;
                if (half) { v = bal1 ? v1 : INF; vi = base + s1; }
                else      { v = bal0 ? v0 : INF; vi = base + s0; }
                unsigned ble = __ballot_sync(FULL, L <= v);
                int pos_ = __popc((ble >> hsh) & 0xFFFFu);
                float Lup = __shfl_up_sync(FULL, L, 1);
                int  LIup = __shfl_up_sync(FULL, LI, 1);
                if (lh == pos_)      { L = v;   LI = vi;   }
                else if (lh > pos_)  { L = Lup; LI = LIup; }
                tp0 = fminf(t0e, __shfl_sync(FULL, L, 15));
                tp1 = fminf(t1e, __shfl_sync(FULL, L, 31));
                bal0 &= bal0 - 1;
                bal1 &= bal1 - 1;
            }
        }
    }
    int q = q0 + half;
    g_knn[q * KNN + lh] = batch * NPTS + LI;
}

// ---------------------------------------------------------------------------
// conv1 (exact R13 body): fused y = w2a[0:32]^T x1 + b2a; writes PPF feats.
// ---------------------------------------------------------------------------
__global__ __launch_bounds__(256) void conv1_kernel(
    const float* __restrict__ pos, const float* __restrict__ nrm,
    const float* __restrict__ w1a, const float* __restrict__ b1a,
    const float* __restrict__ w1b, const float* __restrict__ b1b,
    const float* __restrict__ w2a, const float* __restrict__ b2a)
{
    __shared__ float4 sf[8][20];
    __shared__ float  sh[8][17][32];
    int warp = threadIdx.x >> 5;
    int lane = threadIdx.x & 31;
    int i    = blockIdx.x * 8 + warp;

    float wa0 = w1a[0 * 32 + lane], wa1 = w1a[1 * 32 + lane];
    float wa2 = w1a[2 * 32 + lane], wa3 = w1a[3 * 32 + lane];
    float ba  = b1a[lane];
    float wb[32];
#pragma unroll
    for (int k = 0; k < 32; k++) wb[k] = w1b[k * 32 + lane];
    float bb = b1b[lane];

    float pix = pos[3 * i + 0], piy = pos[3 * i + 1], piz = pos[3 * i + 2];
    float nix = nrm[3 * i + 0], niy = nrm[3 * i + 1], niz = nrm[3 * i + 2];

    int j = (lane < KNN) ? g_knn[i * KNN + lane] : i;   // lane16 = self loop
    float pjx = pos[3 * j + 0], pjy = pos[3 * j + 1], pjz = pos[3 * j + 2];
    float njx = nrm[3 * j + 0], njy = nrm[3 * j + 1], njz = nrm[3 * j + 2];

    float px = pjx - pix, py = pjy - piy, pz = pjz - piz;
    float f0 = safe_norm3(px, py, pz);
    float f1 = angle3(nix, niy, niz, px, py, pz);
    float f2 = angle3(njx, njy, njz, px, py, pz);
    float f3 = angle3(nix, niy, niz, njx, njy, njz);
    if (lane < 17) {
        float4 f = make_float4(f0, f1, f2, f3);
        sf[warp][lane] = f;
        g_feat[i * 17 + lane] = f;
    }
    __syncwarp();

    for (int e = 0; e < 17; e++) {
        float4 f = sf[warp][e];
        float h = ba;
        h = fmaf(f.x, wa0, h); h = fmaf(f.y, wa1, h);
        h = fmaf(f.z, wa2, h); h = fmaf(f.w, wa3, h);
        sh[warp][e][lane] = fmaxf(h, 0.f);
    }
    __syncwarp();

    float best = -CUDART_INF_F;
    for (int e = 0; e < 17; e++) {
        float o0 = bb, o1 = 0.f, o2 = 0.f, o3 = 0.f;
        const float4* hv4 = (const float4*)sh[warp][e];
#pragma unroll
        for (int m = 0; m < 8; m++) {
            float4 hv = hv4[m];
            o0 = fmaf(hv.x, wb[4 * m + 0], o0);
            o1 = fmaf(hv.y, wb[4 * m + 1], o1);
            o2 = fmaf(hv.z, wb[4 * m + 2], o2);
            o3 = fmaf(hv.w, wb[4 * m + 3], o3);
        }
        best = fmaxf(best, (o0 + o1) + (o2 + o3));
    }
    float x1v = fmaxf(best, 0.f);

    sh[warp][0][lane] = x1v;
    __syncwarp();
    float w2[32];
#pragma unroll
    for (int k = 0; k < 32; k++) w2[k] = w2a[k * 32 + lane];
    float a0 = b2a[lane], a1 = 0.f, a2 = 0.f, a3 = 0.f;
    const float4* xv4 = (const float4*)sh[warp][0];
#pragma unroll
    for (int m = 0; m < 8; m++) {
        float4 xv = xv4[m];
        a0 = fmaf(xv.x, w2[4 * m + 0], a0);
        a1 = fmaf(xv.y, w2[4 * m + 1], a1);
        a2 = fmaf(xv.z, w2[4 * m + 2], a2);
        a3 = fmaf(xv.w, w2[4 * m + 3], a3);
    }
    g_y[i * CH + lane] = (a0 + a1) + (a2 + a3);
}

// ---------------------------------------------------------------------------
// conv2 (exact R13 body) + fused pool + last-block fc.
// ---------------------------------------------------------------------------
__global__ __launch_bounds__(256) void conv2_kernel(
    const float* __restrict__ w2a,
    const float* __restrict__ w2b, const float* __restrict__ b2b,
    const float* __restrict__ wc, const float* __restrict__ bc,
    float* __restrict__ out)
{
    __shared__ int   si[8][20];
    __shared__ float sh[8][17][32];
    __shared__ float red[8][32];
    __shared__ int   slast;
    int warp = threadIdx.x >> 5;
    int lane = threadIdx.x & 31;
    int i    = blockIdx.x * 8 + warp;

    float wa32 = w2a[32 * 32 + lane], wa33 = w2a[33 * 32 + lane];
    float wa34 = w2a[34 * 32 + lane], wa35 = w2a[35 * 32 + lane];
    float wb[32];
#pragma unroll
    for (int k = 0; k < 32; k++) wb[k] = w2b[k * 32 + lane];
    float bb = b2b[lane];

    int j = (lane < KNN) ? g_knn[i * KNN + lane] : i;
    if (lane < 17) si[warp][lane] = j;
    __syncwarp();

    float yv[17];
#pragma unroll
    for (int e = 0; e < 17; e++)
        yv[e] = g_y[si[warp][e] * CH + lane];

#pragma unroll
    for (int e = 0; e < 17; e++) {
        float4 f = g_feat[i * 17 + e];
        float h = yv[e];
        h = fmaf(f.x, wa32, h); h = fmaf(f.y, wa33, h);
        h = fmaf(f.z, wa34, h); h = fmaf(f.w, wa35, h);
        sh[warp][e][lane] = fmaxf(h, 0.f);
    }
    __syncwarp();

    float best = -CUDART_INF_F;
    for (int e = 0; e < 17; e++) {
        float o0 = bb, o1 = 0.f, o2 = 0.f, o3 = 0.f;
        const float4* hv4 = (const float4*)sh[warp][e];
#pragma unroll
        for (int m = 0; m < 8; m++) {
            float4 hv = hv4[m];
            o0 = fmaf(hv.x, wb[4 * m + 0], o0);
            o1 = fmaf(hv.y, wb[4 * m + 1], o1);
            o2 = fmaf(hv.z, wb[4 * m + 2], o2);
            o3 = fmaf(hv.w, wb[4 * m + 3], o3);
        }
        best = fmaxf(best, (o0 + o1) + (o2 + o3));
    }
    red[warp][lane] = fmaxf(best, 0.f);
    __syncthreads();

    if (warp == 0) {
        float m = red[0][lane];
#pragma unroll
        for (int r = 1; r < 8; r++) m = fmaxf(m, red[r][lane]);
        int b = (blockIdx.x * 8) >> 12;
        atomicMax((int*)&g_pool[b * CH + lane], __float_as_int(m));
    }
    // last-block fc: out = g_pool @ wc + bc
    __threadfence();
    if (threadIdx.x == 0)
        slast = (atomicAdd(&g_done, 1) == (int)gridDim.x - 1);
    __syncthreads();
    if (slast) {
        for (int t = threadIdx.x; t < NB * NCLS; t += blockDim.x) {
            int b = t / NCLS, o = t % NCLS;
            float acc = bc[o];
#pragma unroll
            for (int c = 0; c < CH; c++)
                acc = fmaf(g_pool[b * CH + c], wc[c * NCLS + o], acc);
            out[t] = acc;
        }
    }
}

extern "C" void kernel_launch(void* const* d_in, const int* in_sizes, int n_in,
                              void* d_out, int out_size) {
    const float* pos = (const float*)d_in[0];
    const float* nrm = (const float*)d_in[1];
    const float* w1a = (const float*)d_in[3];
    const float* b1a = (const float*)d_in[4];
    const float* w1b = (const float*)d_in[5];
    const float* b1b = (const float*)d_in[6];
    const float* w2a = (const float*)d_in[7];
    const float* b2a = (const float*)d_in[8];
    const float* w2b = (const float*)d_in[9];
    const float* b2b = (const float*)d_in[10];
    const float* wc  = (const float*)d_in[11];
    const float* bc  = (const float*)d_in[12];
    float* out = (float*)d_out;

    knn_kernel<<<MPTS / 16, 256>>>(pos);                                  // 1
    conv1_kernel<<<MPTS / 8, 256>>>(pos, nrm, w1a, b1a, w1b, b1b, w2a, b2a); // 2
    conv2_kernel<<<MPTS / 8, 256>>>(w2a, w2b, b2b, wc, bc, out);          // 3
}

// round 17
// speedup vs baseline: 1.0263x; 1.0263x over previous
#include <cuda_runtime.h>
#include <math_constants.h>

#define NB 8
#define NPTS 4096
#define KNN 16
#define MPTS (NB * NPTS)
#define CH 32
#define NCLS 40

__device__ int    g_knn[MPTS * KNN];
__device__ float  g_y[MPTS * CH];
__device__ float4 g_feat[MPTS * 17];
__device__ float  g_pool[NB * CH];

__device__ __forceinline__ float safe_norm3(float x, float y, float z) {
    float s = x * x + y * y + z * z;
    return s > 0.f ? sqrtf(s) : 0.f;
}

__device__ __forceinline__ float angle3(float ax, float ay, float az,
                                        float bx, float by, float bz) {
    float cx = ay * bz - az * by;
    float cy = az * bx - ax * bz;
    float cz = ax * by - ay * bx;
    float cn = safe_norm3(cx, cy, cz);
    float d  = ax * bx + ay * by + az * bz;
    bool ok = (cn > 0.f) || (d != 0.f);
    return ok ? atan2f(cn, d) : 0.f;
}

__global__ void pool_init_kernel() {
    int t = threadIdx.x;
    if (t < NB * CH) g_pool[t] = 0.f;
}

// ---------------------------------------------------------------------------
// kNN v8b (exact R13 winner): two-pass threshold-primed warp-select.
// ---------------------------------------------------------------------------
__global__ __launch_bounds__(256) void knn_kernel(const float* __restrict__ pos) {
    const unsigned FULL = 0xFFFFFFFFu;
    const float INF = CUDART_INF_F;
    int lane = threadIdx.x & 31;
    int warp = threadIdx.x >> 5;
    int half = lane >> 4;
    int lh   = lane & 15;
    int hsh  = half << 4;

    int qbase = blockIdx.x * 16;
    int q0    = qbase + warp * 2;          // even
    int batch = blockIdx.x >> 8;
    int q0l   = q0 & (NPTS - 1);
    int q1l   = q0l + 1;
    int selfb = q0l & ~31;

    float p0x = pos[3 * q0 + 0], p0y = pos[3 * q0 + 1], p0z = pos[3 * q0 + 2];
    float p1x = pos[3 * q0 + 3], p1y = pos[3 * q0 + 4], p1z = pos[3 * q0 + 5];
    float m2x0 = -2.f * p0x, m2y0 = -2.f * p0y, m2z0 = -2.f * p0z;
    float m2x1 = -2.f * p1x, m2y1 = -2.f * p1y, m2z1 = -2.f * p1z;

    const float* bp = pos + (size_t)batch * NPTS * 3;
    __shared__ float4 tile[1024];          // 16 KB

    // pass 1: per-lane running mins
    float min0 = INF, min1 = INF;
    for (int t = 0; t < NPTS; t += 1024) {
        __syncthreads();
#pragma unroll
        for (int u = 0; u < 4; u++) {
            int p = t + threadIdx.x + u * 256;
            float cx = bp[3 * p + 0], cy = bp[3 * p + 1], cz = bp[3 * p + 2];
            tile[threadIdx.x + u * 256] =
                make_float4(cx, cy, cz, cx * cx + cy * cy + cz * cz);
        }
        __syncthreads();
#pragma unroll 4
        for (int s = 0; s < 32; s++) {
            int base = t + s * 32;
            float4 c = tile[s * 32 + lane];
            float d0 = fmaf(c.x, m2x0, fmaf(c.y, m2y0, fmaf(c.z, m2z0, c.w)));
            float d1 = fmaf(c.x, m2x1, fmaf(c.y, m2y1, fmaf(c.z, m2z1, c.w)));
            if (base == selfb) {
                int cl = base + lane;
                if (cl == q0l) d0 = INF;
                if (cl == q1l) d1 = INF;
            }
            min0 = fminf(min0, d0);
            min1 = fminf(min1, d1);
        }
    }

    // tau: 16th smallest of the 32 lane-mins
    float L = INF;
#pragma unroll 8
    for (int src = 0; src < 32; src++) {
        float v0 = __shfl_sync(FULL, min0, src);
        float v1 = __shfl_sync(FULL, min1, src);
        float v = half ? v1 : v0;
        unsigned ble = __ballot_sync(FULL, L <= v);
        int pos_ = __popc((ble >> hsh) & 0xFFFFu);
        float Lup = __shfl_up_sync(FULL, L, 1);
        if (lh == pos_)      L = v;
        else if (lh > pos_)  L = Lup;
    }
    float t0e = nextafterf(__shfl_sync(FULL, L, 15), INF);
    float t1e = nextafterf(__shfl_sync(FULL, L, 31), INF);

    // pass 2: exact selection under primed threshold
    L = INF;
    int LI = batch * NPTS;
    float tp0 = t0e, tp1 = t1e;

    for (int t = 0; t < NPTS; t += 1024) {
        __syncthreads();
#pragma unroll
        for (int u = 0; u < 4; u++) {
            int p = t + threadIdx.x + u * 256;
            float cx = bp[3 * p + 0], cy = bp[3 * p + 1], cz = bp[3 * p + 2];
            tile[threadIdx.x + u * 256] =
                make_float4(cx, cy, cz, cx * cx + cy * cy + cz * cz);
        }
        __syncthreads();
#pragma unroll 4
        for (int s = 0; s < 32; s++) {
            int base = t + s * 32;
            float4 c = tile[s * 32 + lane];
            float d0 = fmaf(c.x, m2x0, fmaf(c.y, m2y0, fmaf(c.z, m2z0, c.w)));
            float d1 = fmaf(c.x, m2x1, fmaf(c.y, m2y1, fmaf(c.z, m2z1, c.w)));
            if (base == selfb) {
                int cl = base + lane;
                if (cl == q0l) d0 = INF;
                if (cl == q1l) d1 = INF;
            }
            unsigned bal0 = __ballot_sync(FULL, d0 < tp0);
            unsigned bal1 = __ballot_sync(FULL, d1 < tp1);
            while (bal0 | bal1) {
                int s0 = __ffs(bal0) - 1;
                int s1 = __ffs(bal1) - 1;
                float v0 = __shfl_sync(FULL, d0, bal0 ? s0 : 0);
                float v1 = __shfl_sync(FULL, d1, bal1 ? s1 : 0);
                float v;
                int   vi;
                if (half) { v = bal1 ? v1 : INF; vi = base + s1; }
                else      { v = bal0 ? v0 : INF; vi = base + s0; }
                unsigned ble = __ballot_sync(FULL, L <= v);
                int pos_ = __popc((ble >> hsh) & 0xFFFFu);
                float Lup = __shfl_up_sync(FULL, L, 1);
                int  LIup = __shfl_up_sync(FULL, LI, 1);
                if (lh == pos_)      { L = v;   LI = vi;   }
                else if (lh > pos_)  { L = Lup; LI = LIup; }
                tp0 = fminf(t0e, __shfl_sync(FULL, L, 15));
                tp1 = fminf(t1e, __shfl_sync(FULL, L, 31));
                bal0 &= bal0 - 1;
                bal1 &= bal1 - 1;
            }
        }
    }
    int q = q0 + half;
    g_knn[q * KNN + lh] = batch * NPTS + LI;
}

// ---------------------------------------------------------------------------
// conv1 (exact R13 body): fused y = w2a[0:32]^T x1 + b2a; writes PPF feats.
// ---------------------------------------------------------------------------
__global__ __launch_bounds__(256) void conv1_kernel(
    const float* __restrict__ pos, const float* __restrict__ nrm,
    const float* __restrict__ w1a, const float* __restrict__ b1a,
    const float* __restrict__ w1b, const float* __restrict__ b1b,
    const float* __restrict__ w2a, const float* __restrict__ b2a)
{
    __shared__ float4 sf[8][20];
    __shared__ float  sh[8][17][32];
    int warp = threadIdx.x >> 5;
    int lane = threadIdx.x & 31;
    int i    = blockIdx.x * 8 + warp;

    float wa0 = w1a[0 * 32 + lane], wa1 = w1a[1 * 32 + lane];
    float wa2 = w1a[2 * 32 + lane], wa3 = w1a[3 * 32 + lane];
    float ba  = b1a[lane];
    float wb[32];
#pragma unroll
    for (int k = 0; k < 32; k++) wb[k] = w1b[k * 32 + lane];
    float bb = b1b[lane];

    float pix = pos[3 * i + 0], piy = pos[3 * i + 1], piz = pos[3 * i + 2];
    float nix = nrm[3 * i + 0], niy = nrm[3 * i + 1], niz = nrm[3 * i + 2];

    int j = (lane < KNN) ? g_knn[i * KNN + lane] : i;   // lane16 = self loop
    float pjx = pos[3 * j + 0], pjy = pos[3 * j + 1], pjz = pos[3 * j + 2];
    float njx = nrm[3 * j + 0], njy = nrm[3 * j + 1], njz = nrm[3 * j + 2];

    float px = pjx - pix, py = pjy - piy, pz = pjz - piz;
    float f0 = safe_norm3(px, py, pz);
    float f1 = angle3(nix, niy, niz, px, py, pz);
    float f2 = angle3(njx, njy, njz, px, py, pz);
    float f3 = angle3(nix, niy, niz, njx, njy, njz);
    if (lane < 17) {
        float4 f = make_float4(f0, f1, f2, f3);
        sf[warp][lane] = f;
        g_feat[i * 17 + lane] = f;
    }
    __syncwarp();

    for (int e = 0; e < 17; e++) {
        float4 f = sf[warp][e];
        float h = ba;
        h = fmaf(f.x, wa0, h); h = fmaf(f.y, wa1, h);
        h = fmaf(f.z, wa2, h); h = fmaf(f.w, wa3, h);
        sh[warp][e][lane] = fmaxf(h, 0.f);
    }
    __syncwarp();

    float best = -CUDART_INF_F;
    for (int e = 0; e < 17; e++) {
        float o0 = bb, o1 = 0.f, o2 = 0.f, o3 = 0.f;
        const float4* hv4 = (const float4*)sh[warp][e];
#pragma unroll
        for (int m = 0; m < 8; m++) {
            float4 hv = hv4[m];
            o0 = fmaf(hv.x, wb[4 * m + 0], o0);
            o1 = fmaf(hv.y, wb[4 * m + 1], o1);
            o2 = fmaf(hv.z, wb[4 * m + 2], o2);
            o3 = fmaf(hv.w, wb[4 * m + 3], o3);
        }
        best = fmaxf(best, (o0 + o1) + (o2 + o3));
    }
    float x1v = fmaxf(best, 0.f);

    sh[warp][0][lane] = x1v;
    __syncwarp();
    float w2[32];
#pragma unroll
    for (int k = 0; k < 32; k++) w2[k] = w2a[k * 32 + lane];
    float a0 = b2a[lane], a1 = 0.f, a2 = 0.f, a3 = 0.f;
    const float4* xv4 = (const float4*)sh[warp][0];
#pragma unroll
    for (int m = 0; m < 8; m++) {
        float4 xv = xv4[m];
        a0 = fmaf(xv.x, w2[4 * m + 0], a0);
        a1 = fmaf(xv.y, w2[4 * m + 1], a1);
        a2 = fmaf(xv.z, w2[4 * m + 2], a2);
        a3 = fmaf(xv.w, w2[4 * m + 3], a3);
    }
    g_y[i * CH + lane] = (a0 + a1) + (a2 + a3);
}

// ---------------------------------------------------------------------------
// conv2 v2: warp = 2 nodes; lanes 0-15 = node A (channels 2lh,2lh+1),
// lanes 16-31 = node B. Layer-2 LDS.128 count per node halves (each
// broadcast set feeds 64 FMA). Node-B h region offset by +4 floats so the
// dual half-warp broadcast is bank-conflict-free.
// ---------------------------------------------------------------------------
#define HSTRIDE (17 * 32 + 4)   // floats per node's h region (pad 16B)

__global__ __launch_bounds__(256) void conv2_kernel(
    const float* __restrict__ w2a,
    const float* __restrict__ w2b, const float* __restrict__ b2b)
{
    __shared__ int   si[8][2][20];
    __shared__ float sh[8][2 * HSTRIDE];
    __shared__ float red[8][2][32];
    int warp = threadIdx.x >> 5;
    int lane = threadIdx.x & 31;
    int half = lane >> 4;
    int lh   = lane & 15;
    int c0   = 2 * lh;                        // my first channel

    int iA   = blockIdx.x * 16 + warp * 2;    // node for lanes 0-15
    int node = iA + half;                      // my node

    // weights for my 2 channels
    float wa32x = w2a[32 * 32 + c0], wa32y = w2a[32 * 32 + c0 + 1];
    float wa33x = w2a[33 * 32 + c0], wa33y = w2a[33 * 32 + c0 + 1];
    float wa34x = w2a[34 * 32 + c0], wa34y = w2a[34 * 32 + c0 + 1];
    float wa35x = w2a[35 * 32 + c0], wa35y = w2a[35 * 32 + c0 + 1];
    float2 wb2[32];
#pragma unroll
    for (int k = 0; k < 32; k++)
        wb2[k] = ((const float2*)&w2b[k * 32])[lh];
    float bbx = b2b[c0], bby = b2b[c0 + 1];

    // neighbor indices for both nodes (17 incl. self)
    if (lane < 17) {
        si[warp][0][lane] = (lane < KNN) ? g_knn[iA * KNN + lane] : iA;
        si[warp][1][lane] = (lane < KNN) ? g_knn[(iA + 1) * KNN + lane] : iA + 1;
    }
    __syncwarp();

    float* hbase = &sh[warp][half * HSTRIDE];

    // layer 1: h for my node's 2 channels, all 17 edges
#pragma unroll
    for (int e = 0; e < 17; e++) {
        int src = si[warp][half][e];
        float2 yv = ((const float2*)&g_y[src * CH])[lh];
        float4 f  = g_feat[node * 17 + e];
        float hx = yv.x, hy = yv.y;
        hx = fmaf(f.x, wa32x, hx); hy = fmaf(f.x, wa32y, hy);
        hx = fmaf(f.y, wa33x, hx); hy = fmaf(f.y, wa33y, hy);
        hx = fmaf(f.z, wa34x, hx); hy = fmaf(f.z, wa34y, hy);
        hx = fmaf(f.w, wa35x, hx); hy = fmaf(f.w, wa35y, hy);
        ((float2*)&hbase[e * 32])[lh] = make_float2(fmaxf(hx, 0.f), fmaxf(hy, 0.f));
    }
    __syncwarp();

    // layer 2 + max over edges (2 output channels per lane)
    float bestx = -CUDART_INF_F, besty = -CUDART_INF_F;
    for (int e = 0; e < 17; e++) {
        const float4* hv4 = (const float4*)&hbase[e * 32];
        float ox0 = bbx, ox1 = 0.f, oy0 = bby, oy1 = 0.f;
#pragma unroll
        for (int m = 0; m < 8; m++) {
            float4 hv = hv4[m];
            ox0 = fmaf(hv.x, wb2[4 * m + 0].x, ox0);
            oy0 = fmaf(hv.x, wb2[4 * m + 0].y, oy0);
            ox1 = fmaf(hv.y, wb2[4 * m + 1].x, ox1);
            oy1 = fmaf(hv.y, wb2[4 * m + 1].y, oy1);
            ox0 = fmaf(hv.z, wb2[4 * m + 2].x, ox0);
            oy0 = fmaf(hv.z, wb2[4 * m + 2].y, oy0);
            ox1 = fmaf(hv.w, wb2[4 * m + 3].x, ox1);
            oy1 = fmaf(hv.w, wb2[4 * m + 3].y, oy1);
        }
        bestx = fmaxf(bestx, ox0 + ox1);
        besty = fmaxf(besty, oy0 + oy1);
    }
    red[warp][half][c0]     = fmaxf(bestx, 0.f);
    red[warp][half][c0 + 1] = fmaxf(besty, 0.f);
    __syncthreads();

    // block pool: 16 nodes, all same batch
    if (threadIdx.x < 32) {
        float m = red[0][0][lane];
#pragma unroll
        for (int w = 0; w < 8; w++) {
            m = fmaxf(m, red[w][0][lane]);
            m = fmaxf(m, red[w][1][lane]);
        }
        int b = (blockIdx.x * 16) >> 12;
        atomicMax((int*)&g_pool[b * CH + lane], __float_as_int(m));
    }
}

__global__ void fc_kernel(const float* __restrict__ wc,
                          const float* __restrict__ bc,
                          float* __restrict__ out) {
    int t = threadIdx.x;
    if (t < NB * NCLS) {
        int b = t / NCLS, o = t % NCLS;
        float acc = bc[o];
#pragma unroll
        for (int c = 0; c < CH; c++)
            acc = fmaf(g_pool[b * CH + c], wc[c * NCLS + o], acc);
        out[t] = acc;
    }
}

extern "C" void kernel_launch(void* const* d_in, const int* in_sizes, int n_in,
                              void* d_out, int out_size) {
    const float* pos = (const float*)d_in[0];
    const float* nrm = (const float*)d_in[1];
    const float* w1a = (const float*)d_in[3];
    const float* b1a = (const float*)d_in[4];
    const float* w1b = (const float*)d_in[5];
    const float* b1b = (const float*)d_in[6];
    const float* w2a = (const float*)d_in[7];
    const float* b2a = (const float*)d_in[8];
    const float* w2b = (const float*)d_in[9];
    const float* b2b = (const float*)d_in[10];
    const float* wc  = (const float*)d_in[11];
    const float* bc  = (const float*)d_in[12];
    float* out = (float*)d_out;

    pool_init_kernel<<<1, 256>>>();            // 1
    knn_kernel<<<MPTS / 16, 256>>>(pos);       // 2
    conv1_kernel<<<MPTS / 8, 256>>>(pos, nrm, w1a, b1a, w1b, b1b, w2a, b2a); // 3
    conv2_kernel<<<MPTS / 16, 256>>>(w2a, w2b, b2b);  // 4 (ncu sample slot)
    fc_kernel<<<1, 320>>>(wc, bc, out);        // 5
}